// round 13
// baseline (speedup 1.0000x reference)
#include <cuda_runtime.h>
#include <math.h>

typedef unsigned long long ull;

// Problem dims
#define BB 64
#define NN 133
#define NROW (BB*NN)      // 8512 (flattened M)
#define F0 75
#define F1 150
#define H1 256
#define H2 128
#define GP1 152           // padded emb output stride
#define GP3 76            // padded gc3 output stride
#define LSTR 136          // edge-list stride

// ---------------- scratch ----------------
__device__ float g_bufA[(size_t)NROW * 256];
__device__ float g_bufB[(size_t)NROW * 256];

__device__ float g_embw[F0 * GP1];
__device__ float g_embb[GP1];
__device__ float g_gc3w[H2 * GP3];
__device__ float g_b3pad[GP3];

__device__ int   g_nz_cnt[NROW];
__device__ ull   g_nz[(size_t)NROW * LSTR];
__device__ int   g_pl_cnt[NROW];
__device__ int   g_pl_idx[(size_t)NROW * LSTR];

// ---------------- f32x2 helpers (sparse kernels only) ----------------
__device__ __forceinline__ ull pk2(float x, float y) {
    ull r;
    asm("mov.b64 %0, {%1, %2};" : "=l"(r) : "f"(x), "f"(y));
    return r;
}
__device__ __forceinline__ void upk2(ull v, float& x, float& y) {
    asm("mov.b64 {%0, %1}, %2;" : "=f"(x), "=f"(y) : "l"(v));
}
#define FMA2(acc, a, b) asm("fma.rn.f32x2 %0, %1, %2, %0;" : "+l"(acc) : "l"(a), "l"(b))

// ---------------- cp.async helpers ----------------
__device__ __forceinline__ unsigned smem_u32p(const void* p) {
    return (unsigned)__cvta_generic_to_shared(p);
}
__device__ __forceinline__ void cp16(unsigned dst, const void* src) {
    asm volatile("cp.async.ca.shared.global [%0], [%1], 16;" :: "r"(dst), "l"(src));
}
__device__ __forceinline__ void cp4(unsigned dst, const void* src) {
    asm volatile("cp.async.ca.shared.global [%0], [%1], 4;" :: "r"(dst), "l"(src));
}
__device__ __forceinline__ void cp_commit() {
    asm volatile("cp.async.commit_group;" ::: "memory");
}
template<int N>
__device__ __forceinline__ void cp_wait() {
    asm volatile("cp.async.wait_group %0;" :: "n"(N) : "memory");
}

// ---------------- build sparse lists + weight padding (fused) ----------------
#define PAD_T0 (F0*GP1)
#define PAD_T1 (PAD_T0 + GP1)
#define PAD_T2 (PAD_T1 + H2*GP3)
#define PAD_T3 (PAD_T2 + GP3)
__global__ void k_build_lists(const float* __restrict__ adj,
                              const float* __restrict__ emb_w, const float* __restrict__ emb_b,
                              const float* __restrict__ gc3_w, const float* __restrict__ gc3_b) {
    // weight padding (striped across the whole grid)
    int gtid = blockIdx.x * blockDim.x + threadIdx.x;
    if (gtid < PAD_T3) {
        int idx = gtid;
        if (idx < PAD_T0) {
            int g = idx % GP1;
            g_embw[idx] = (g < F1) ? emb_w[(idx / GP1) * F1 + g] : 0.0f;
        } else if (idx < PAD_T1) {
            int g = idx - PAD_T0;
            g_embb[g] = (g < F1) ? emb_b[g] : 0.0f;
        } else if (idx < PAD_T2) {
            int j = idx - PAD_T1;
            int g = j % GP3;
            g_gc3w[j] = (g < F0) ? gc3_w[(j / GP3) * F0 + g] : 0.0f;
        } else {
            int g = idx - PAD_T2;
            g_b3pad[g] = (g < F0) ? gc3_b[g] : 0.0f;
        }
    }

    int warp_in_blk = threadIdx.x >> 5;
    int lane = threadIdx.x & 31;
    int wg = blockIdx.x * (blockDim.x >> 5) + warp_in_blk;
    if (wg >= NROW) return;
    const float* arow = adj + (size_t)wg * NN;

    int cnz = 0, cpl = 0;
    int firstj = 0;
    unsigned lt = (1u << lane) - 1u;
    for (int base = 0; base < NN; base += 32) {
        int j = base + lane;
        float a = (j < NN) ? arow[j] : 0.0f;
        bool nz = (j < NN) && (a != 0.0f);
        bool pl = (j < NN) && (a > 1e-5f);
        unsigned mnz = __ballot_sync(0xffffffffu, nz);
        unsigned mpl = __ballot_sync(0xffffffffu, pl);
        if (nz) {
            int pos = cnz + __popc(mnz & lt);
            g_nz[(size_t)wg * LSTR + pos] =
                ((ull)__float_as_uint(a) << 32) | (unsigned)j;
        }
        if (pl) {
            int pos = cpl + __popc(mpl & lt);
            g_pl_idx[(size_t)wg * LSTR + pos] = j;
        }
        if (cpl == 0 && mpl) firstj = base + __ffs(mpl) - 1;
        cnz += __popc(mnz);
        cpl += __popc(mpl);
    }
    int pnz = (cnz + 7) & ~7;
    int ppl = (cpl + 7) & ~7;
    if (lane < pnz - cnz) g_nz[(size_t)wg * LSTR + cnz + lane] = 0ull;
    if (lane < ppl - cpl) g_pl_idx[(size_t)wg * LSTR + cpl + lane] = firstj;
    if (lane == 0) { g_nz_cnt[wg] = pnz; g_pl_cnt[wg] = ppl; }
}

// ---------------- dense GEMM: double-buffered cp.async, R x C tile ----------
// C_[m,g] = A[m,:] @ W[:,g] (+bias, relu); m flattened 0..8511.
// grid (8512/(R*RG)), block (G/C, RG). C in {4,8}.
template<int R, int C>
__global__ void k_dense_db(const float* __restrict__ A, const float* __restrict__ W,
                           const float* __restrict__ bias, float* __restrict__ C_,
                           int K, int AS, int G, int GP, int do_relu) {
    const int KC = 32;
    const int C4 = C / 4;
    extern __shared__ float sm[];
    int BN = blockDim.x * C;                 // == G
    int nrows = R * blockDim.y;
    int stageW = KC * BN;
    int stageA = nrows * KC;
    int stride = stageW + stageA;            // floats per stage

    int m0   = blockIdx.x * nrows;
    int tid  = threadIdx.y * blockDim.x + threadIdx.x;
    int nthr = blockDim.x * blockDim.y;
    int g0   = threadIdx.x * C;
    int nch  = (K + KC - 1) / KC;

    float acc[R][C];
    #pragma unroll
    for (int r = 0; r < R; r++)
        #pragma unroll
        for (int c = 0; c < C; c++) acc[r][c] = 0.0f;

    #define PREFETCH(CH, BUF) do {                                              \
        float* pW = sm + (BUF) * stride;                                        \
        float* pA = pW + stageW;                                                \
        int kc = (CH) * KC;                                                     \
        for (int kk = threadIdx.y; kk < KC; kk += blockDim.y) {                 \
            int k = kc + kk;                                                    \
            _Pragma("unroll")                                                   \
            for (int c4 = 0; c4 < C4; c4++) {                                   \
                float* d = pW + kk * BN + g0 + 4 * c4;                          \
                if (k < K) cp16(smem_u32p(d), W + (size_t)k * G + g0 + 4 * c4); \
                else *reinterpret_cast<float4*>(d) =                            \
                         make_float4(0.f, 0.f, 0.f, 0.f);                       \
            }                                                                   \
        }                                                                       \
        for (int idx = tid; idx < stageA; idx += nthr) {                        \
            int r = idx >> 5, kk = idx & 31;                                    \
            int k = kc + kk;                                                    \
            if (k < K) cp4(smem_u32p(pA + idx), A + (size_t)(m0 + r) * AS + k); \
            else pA[idx] = 0.0f;                                                \
        }                                                                       \
    } while (0)

    PREFETCH(0, 0);
    cp_commit();

    for (int ch = 0; ch < nch; ch++) {
        int buf = ch & 1;
        if (ch + 1 < nch) {
            PREFETCH(ch + 1, buf ^ 1);
            cp_commit();
            cp_wait<1>();
        } else {
            cp_wait<0>();
        }
        __syncthreads();

        const float* sW  = sm + buf * stride;
        const float* sAr = sW + stageW + threadIdx.y * R * KC;
        #pragma unroll 8
        for (int kk = 0; kk < KC; kk++) {
            float4 w[C4];
            #pragma unroll
            for (int c4 = 0; c4 < C4; c4++)
                w[c4] = *reinterpret_cast<const float4*>(sW + kk * BN + g0 + 4 * c4);
            #pragma unroll
            for (int r = 0; r < R; r++) {
                float a = sAr[r * KC + kk];          // warp broadcast
                #pragma unroll
                for (int c4 = 0; c4 < C4; c4++) {
                    acc[r][4*c4+0] = fmaf(a, w[c4].x, acc[r][4*c4+0]);
                    acc[r][4*c4+1] = fmaf(a, w[c4].y, acc[r][4*c4+1]);
                    acc[r][4*c4+2] = fmaf(a, w[c4].z, acc[r][4*c4+2]);
                    acc[r][4*c4+3] = fmaf(a, w[c4].w, acc[r][4*c4+3]);
                }
            }
        }
        __syncthreads();
    }
    #undef PREFETCH

    int i0 = threadIdx.y * R;
    #pragma unroll
    for (int c4 = 0; c4 < C4; c4++) {
        float4 bv = make_float4(0.f, 0.f, 0.f, 0.f);
        if (bias) bv = *reinterpret_cast<const float4*>(bias + g0 + 4 * c4);
        #pragma unroll
        for (int r = 0; r < R; r++) {
            int row = m0 + i0 + r;
            float4 v = make_float4(acc[r][4*c4+0] + bv.x, acc[r][4*c4+1] + bv.y,
                                   acc[r][4*c4+2] + bv.z, acc[r][4*c4+3] + bv.w);
            if (do_relu) {
                v.x = fmaxf(v.x, 0.f); v.y = fmaxf(v.y, 0.f);
                v.z = fmaxf(v.z, 0.f); v.w = fmaxf(v.w, 0.f);
            }
            *reinterpret_cast<float4*>(C_ + (size_t)row * GP + g0 + 4 * c4) = v;
        }
    }
}

// ---------------- spmm + relu, 4 cols/thread, 8-deep gather -----------------
__global__ void k_spmm4(const float* __restrict__ T, const float* __restrict__ bias,
                        float* __restrict__ O, int G) {
    int b = blockIdx.y;
    int i = blockIdx.x * blockDim.y + threadIdx.y;
    if (i >= NN) return;
    int row = b * NN + i;
    int g0 = threadIdx.x * 4;

    int cnt = g_nz_cnt[row];
    const ull* L = g_nz + (size_t)row * LSTR;
    const float* Tb = T + (size_t)b * NN * G + g0;

    ull acc0 = pk2(bias[g0], bias[g0 + 1]);
    ull acc1 = pk2(bias[g0 + 2], bias[g0 + 3]);
    for (int e = 0; e < cnt; e += 8) {
        ull p[8];
        #pragma unroll
        for (int u = 0; u < 8; u++) p[u] = L[e + u];
        ulonglong2 t[8];
        #pragma unroll
        for (int u = 0; u < 8; u++)
            t[u] = *(const ulonglong2*)(Tb + (size_t)(unsigned)p[u] * G);
        #pragma unroll
        for (int u = 0; u < 8; u++) {
            float v = __uint_as_float((unsigned)(p[u] >> 32));
            ull v2 = pk2(v, v);
            FMA2(acc0, t[u].x, v2);
            FMA2(acc1, t[u].y, v2);
        }
    }
    float h0, h1, h2, h3;
    upk2(acc0, h0, h1);
    upk2(acc1, h2, h3);
    float4 r = make_float4(fmaxf(h0, 0.f), fmaxf(h1, 0.f), fmaxf(h2, 0.f), fmaxf(h3, 0.f));
    *reinterpret_cast<float4*>(O + (size_t)row * G + g0) = r;
}

// ---------------- neighbor max-pool, 4 cols/thread, 8-deep ------------------
__global__ void k_pool4(const float* __restrict__ H, float* __restrict__ O, int G) {
    int b = blockIdx.y;
    int i = blockIdx.x * blockDim.y + threadIdx.y;
    if (i >= NN) return;
    int row = b * NN + i;
    int g0 = threadIdx.x * 4;

    int cnt = g_pl_cnt[row];
    const int* ji = g_pl_idx + (size_t)row * LSTR;
    const float4* Hb = reinterpret_cast<const float4*>(H + (size_t)b * NN * G + g0);
    int pitch = G >> 2;

    float4 m = make_float4(0.f, 0.f, 0.f, 0.f);
    for (int e = 0; e < cnt; e += 8) {
        int j[8];
        #pragma unroll
        for (int u = 0; u < 8; u++) j[u] = ji[e + u];
        float4 h[8];
        #pragma unroll
        for (int u = 0; u < 8; u++) h[u] = Hb[(size_t)j[u] * pitch];
        #pragma unroll
        for (int u = 0; u < 8; u++) {
            m.x = fmaxf(m.x, h[u].x);
            m.y = fmaxf(m.y, h[u].y);
            m.z = fmaxf(m.z, h[u].z);
            m.w = fmaxf(m.w, h[u].w);
        }
    }
    reinterpret_cast<float4*>(O + (size_t)row * G + g0)[0] = m;
}

// ---------------- head: gc4 + fc1 + fin + sigmoid ----------
__global__ void k_final(const float* __restrict__ P3,
                        const float* __restrict__ gc4_w,
                        const float* __restrict__ gc4_b,
                        const float* __restrict__ fc1_w,
                        const float* __restrict__ fc1_b,
                        const float* __restrict__ fin_w,
                        const float* __restrict__ fin_b,
                        float* __restrict__ out) {
    int b = blockIdx.x;
    int t = threadIdx.x;
    __shared__ float t4[NN];
    __shared__ float h[NN];
    __shared__ float rr[3];

    if (t < NN) {
        const float* p = P3 + (size_t)(b * NN + t) * GP3;
        float a = 0.0f;
        #pragma unroll
        for (int k = 0; k < F0; k++) a = fmaf(p[k], gc4_w[k], a);
        t4[t] = a;
    }
    __syncthreads();

    if (t < NN) {
        int row = b * NN + t;
        int cnt = g_nz_cnt[row];
        const ull* L = g_nz + (size_t)row * LSTR;
        float acc = gc4_b[0];
        for (int e = 0; e < cnt; e++) {
            ull p = L[e];
            acc = fmaf(__uint_as_float((unsigned)(p >> 32)), t4[(int)(unsigned)p], acc);
        }
        h[t] = fmaxf(acc, 0.0f);
    }
    __syncthreads();

    if (t < 3) {
        float a = fc1_b[t];
        for (int k = 0; k < NN - 1; k++)
            a = fmaf(h[k + 1], fc1_w[k * 3 + t], a);
        rr[t] = a;
    }
    __syncthreads();

    if (t == 0) {
        float z = h[0] * fin_w[0] + rr[0] * fin_w[1] + rr[1] * fin_w[2]
                + rr[2] * fin_w[3] + fin_b[0];
        out[b] = 1.0f / (1.0f + expf(-z));
    }
}

// ---------------- launch ----------------
extern "C" void kernel_launch(void* const* d_in, const int* in_sizes, int n_in,
                              void* d_out, int out_size) {
    const float* x     = (const float*)d_in[0];
    const float* adj   = (const float*)d_in[1];
    const float* emb_w = (const float*)d_in[2];
    const float* emb_b = (const float*)d_in[3];
    const float* gc1_w = (const float*)d_in[4];
    const float* gc1_b = (const float*)d_in[5];
    const float* gc2_w = (const float*)d_in[6];
    const float* gc2_b = (const float*)d_in[7];
    const float* gc3_w = (const float*)d_in[8];
    const float* gc3_b = (const float*)d_in[9];
    const float* gc4_w = (const float*)d_in[10];
    const float* gc4_b = (const float*)d_in[11];
    const float* fc1_w = (const float*)d_in[12];
    const float* fc1_b = (const float*)d_in[13];
    const float* fin_w = (const float*)d_in[14];
    const float* fin_b = (const float*)d_in[15];
    float* out = (float*)d_out;

    float *dA, *dB, *dEw, *dEb, *d3w, *db3;
    cudaGetSymbolAddress((void**)&dA,  g_bufA);
    cudaGetSymbolAddress((void**)&dB,  g_bufB);
    cudaGetSymbolAddress((void**)&dEw, g_embw);
    cudaGetSymbolAddress((void**)&dEb, g_embb);
    cudaGetSymbolAddress((void**)&d3w, g_gc3w);
    cudaGetSymbolAddress((void**)&db3, g_b3pad);

    cudaFuncSetAttribute(k_dense_db<4, 8>,
                         cudaFuncAttributeMaxDynamicSharedMemorySize, 75776);
    cudaFuncSetAttribute(k_dense_db<4, 4>,
                         cudaFuncAttributeMaxDynamicSharedMemorySize, 75776);

    // 0) sparse lists + weight padding (fused)
    {
        int warps_per_blk = 8;
        int blocks = (NROW + warps_per_blk - 1) / warps_per_blk;
        k_build_lists<<<blocks, warps_per_blk * 32>>>(adj, emb_w, emb_b, gc3_w, gc3_b);
    }

    const int KC = 32;
    int sm_emb = 2 * (KC * GP1 + 32 * KC) * 4;   // 47104
    int sm_gc1 = 2 * (KC * H1  + 32 * KC) * 4;   // 73728
    int sm_gc2 = 2 * (KC * H2  + 64 * KC) * 4;   // 49152
    int sm_gc3 = 2 * (KC * GP3 + 64 * KC) * 4;   // 35840

    // 1) emb: dA = relu(x @ embw_pad + embb_pad)   [8512,152]  C=8
    k_dense_db<4, 8><<<266, dim3(19, 8), sm_emb>>>(x, dEw, dEb, dA, F0, F0, GP1, GP1, 1);
    // 2) dB = dA @ gc1_w                           [8512,256]  C=8
    k_dense_db<4, 8><<<266, dim3(32, 8), sm_gc1>>>(dA, gc1_w, nullptr, dB, F1, GP1, H1, H1, 0);
    // 3) dA = relu(adj.dB + gc1_b)
    k_spmm4<<<dim3(34, BB), dim3(64, 4)>>>(dB, gc1_b, dA, H1);
    // 4) dB = pool(dA)
    k_pool4<<<dim3(34, BB), dim3(64, 4)>>>(dA, dB, H1);
    // 5) dA = dB @ gc2_w                           [8512,128]  C=8
    k_dense_db<4, 8><<<133, dim3(16, 16), sm_gc2>>>(dB, gc2_w, nullptr, dA, H1, H1, H2, H2, 0);
    // 6) dB = relu(adj.dA + gc2_b)
    k_spmm4<<<dim3(17, BB), dim3(32, 8)>>>(dA, gc2_b, dB, H2);
    // 7) dA = pool(dB)
    k_pool4<<<dim3(17, BB), dim3(32, 8)>>>(dB, dA, H2);
    // 8) dB = dA @ gc3w_pad                        [8512,76]   C=4
    k_dense_db<4, 4><<<133, dim3(19, 16), sm_gc3>>>(dA, d3w, nullptr, dB, H2, H2, GP3, GP3, 0);
    // 9) dA = relu(adj.dB + b3pad)                 [.,76]
    k_spmm4<<<dim3(17, BB), dim3(19, 8)>>>(dB, db3, dA, GP3);
    // 10) dB = pool(dA)                            [.,76]
    k_pool4<<<dim3(17, BB), dim3(19, 8)>>>(dA, dB, GP3);
    // 11) head
    k_final<<<BB, 160>>>(dB, gc4_w, gc4_b, fc1_w, fc1_b, fin_w, fin_b, out);
}

// round 14
// speedup vs baseline: 1.1475x; 1.1475x over previous
#include <cuda_runtime.h>
#include <math.h>

typedef unsigned long long ull;

// Problem dims
#define BB 64
#define NN 133
#define NROW (BB*NN)      // 8512 real rows
#define MPAD 9472         // 64 * 148: padded M => dense grid = 148 = 1 block/SM
#define F0 75
#define F1 150
#define H1 256
#define H2 128
#define GP1 152           // padded emb output stride
#define GP3 76            // padded gc3 output stride
#define LSTR 136          // edge-list stride

// ---------------- scratch (sized for padded M) ----------------
__device__ float g_bufA[(size_t)MPAD * 256];
__device__ float g_bufB[(size_t)MPAD * 256];

__device__ float g_embw[F0 * GP1];
__device__ float g_embb[GP1];
__device__ float g_gc3w[H2 * GP3];
__device__ float g_b3pad[GP3];

__device__ int   g_nz_cnt[NROW];
__device__ ull   g_nz[(size_t)NROW * LSTR];
__device__ int   g_pl_cnt[NROW];
__device__ int   g_pl_idx[(size_t)NROW * LSTR];

// ---------------- f32x2 helpers (sparse kernels only) ----------------
__device__ __forceinline__ ull pk2(float x, float y) {
    ull r;
    asm("mov.b64 %0, {%1, %2};" : "=l"(r) : "f"(x), "f"(y));
    return r;
}
__device__ __forceinline__ void upk2(ull v, float& x, float& y) {
    asm("mov.b64 {%0, %1}, %2;" : "=f"(x), "=f"(y) : "l"(v));
}
#define FMA2(acc, a, b) asm("fma.rn.f32x2 %0, %1, %2, %0;" : "+l"(acc) : "l"(a), "l"(b))

// ---------------- cp.async helpers ----------------
__device__ __forceinline__ unsigned smem_u32p(const void* p) {
    return (unsigned)__cvta_generic_to_shared(p);
}
__device__ __forceinline__ void cp16(unsigned dst, const void* src) {
    asm volatile("cp.async.ca.shared.global [%0], [%1], 16;" :: "r"(dst), "l"(src));
}
__device__ __forceinline__ void cp4(unsigned dst, const void* src) {
    asm volatile("cp.async.ca.shared.global [%0], [%1], 4;" :: "r"(dst), "l"(src));
}
__device__ __forceinline__ void cp_commit() {
    asm volatile("cp.async.commit_group;" ::: "memory");
}
template<int N>
__device__ __forceinline__ void cp_wait() {
    asm volatile("cp.async.wait_group %0;" :: "n"(N) : "memory");
}

// ---------------- build sparse lists + weight padding (fused) ----------------
#define PAD_T0 (F0*GP1)
#define PAD_T1 (PAD_T0 + GP1)
#define PAD_T2 (PAD_T1 + H2*GP3)
#define PAD_T3 (PAD_T2 + GP3)
__global__ void k_build_lists(const float* __restrict__ adj,
                              const float* __restrict__ emb_w, const float* __restrict__ emb_b,
                              const float* __restrict__ gc3_w, const float* __restrict__ gc3_b) {
    int gtid = blockIdx.x * blockDim.x + threadIdx.x;
    if (gtid < PAD_T3) {
        int idx = gtid;
        if (idx < PAD_T0) {
            int g = idx % GP1;
            g_embw[idx] = (g < F1) ? emb_w[(idx / GP1) * F1 + g] : 0.0f;
        } else if (idx < PAD_T1) {
            int g = idx - PAD_T0;
            g_embb[g] = (g < F1) ? emb_b[g] : 0.0f;
        } else if (idx < PAD_T2) {
            int j = idx - PAD_T1;
            int g = j % GP3;
            g_gc3w[j] = (g < F0) ? gc3_w[(j / GP3) * F0 + g] : 0.0f;
        } else {
            int g = idx - PAD_T2;
            g_b3pad[g] = (g < F0) ? gc3_b[g] : 0.0f;
        }
    }

    int warp_in_blk = threadIdx.x >> 5;
    int lane = threadIdx.x & 31;
    int wg = blockIdx.x * (blockDim.x >> 5) + warp_in_blk;
    if (wg >= NROW) return;
    const float* arow = adj + (size_t)wg * NN;

    int cnz = 0, cpl = 0;
    int firstj = 0;
    unsigned lt = (1u << lane) - 1u;
    for (int base = 0; base < NN; base += 32) {
        int j = base + lane;
        float a = (j < NN) ? arow[j] : 0.0f;
        bool nz = (j < NN) && (a != 0.0f);
        bool pl = (j < NN) && (a > 1e-5f);
        unsigned mnz = __ballot_sync(0xffffffffu, nz);
        unsigned mpl = __ballot_sync(0xffffffffu, pl);
        if (nz) {
            int pos = cnz + __popc(mnz & lt);
            g_nz[(size_t)wg * LSTR + pos] =
                ((ull)__float_as_uint(a) << 32) | (unsigned)j;
        }
        if (pl) {
            int pos = cpl + __popc(mpl & lt);
            g_pl_idx[(size_t)wg * LSTR + pos] = j;
        }
        if (cpl == 0 && mpl) firstj = base + __ffs(mpl) - 1;
        cnz += __popc(mnz);
        cpl += __popc(mpl);
    }
    int pnz = (cnz + 7) & ~7;
    int ppl = (cpl + 7) & ~7;
    if (lane < pnz - cnz) g_nz[(size_t)wg * LSTR + cnz + lane] = 0ull;
    if (lane < ppl - cpl) g_pl_idx[(size_t)wg * LSTR + cpl + lane] = firstj;
    if (lane == 0) { g_nz_cnt[wg] = pnz; g_pl_cnt[wg] = ppl; }
}

// ---------------- dense GEMM: double-buffered cp.async, R x 4 tile ----------
// C_[m,g] = A[m,:] @ W[:,g] (+bias, relu); m in [0, MPAD); rows >= NROW are
// zero-fed and written only to padded scratch (never read downstream).
// grid (MPAD/(R*RG)) = 148, block (G/4, RG).
template<int R>
__global__ void k_dense_db(const float* __restrict__ A, const float* __restrict__ W,
                           const float* __restrict__ bias, float* __restrict__ C_,
                           int K, int AS, int G, int GP, int do_relu, int arows) {
    const int KC = 32;
    extern __shared__ float sm[];
    int BN = blockDim.x * 4;                 // == G
    int nrows = R * blockDim.y;
    int stageW = KC * BN;
    int stageA = nrows * KC;
    int stride = stageW + stageA;

    int m0   = blockIdx.x * nrows;
    int tid  = threadIdx.y * blockDim.x + threadIdx.x;
    int nthr = blockDim.x * blockDim.y;
    int g0   = threadIdx.x * 4;
    int nch  = (K + KC - 1) / KC;

    float acc[R][4];
    #pragma unroll
    for (int r = 0; r < R; r++)
        #pragma unroll
        for (int c = 0; c < 4; c++) acc[r][c] = 0.0f;

    #define PREFETCH(CH, BUF) do {                                              \
        float* pW = sm + (BUF) * stride;                                        \
        float* pA = pW + stageW;                                                \
        int kc = (CH) * KC;                                                     \
        for (int kk = threadIdx.y; kk < KC; kk += blockDim.y) {                 \
            int k = kc + kk;                                                    \
            float* d = pW + kk * BN + g0;                                       \
            if (k < K) cp16(smem_u32p(d), W + (size_t)k * G + g0);              \
            else *reinterpret_cast<float4*>(d) = make_float4(0.f,0.f,0.f,0.f);  \
        }                                                                       \
        for (int idx = tid; idx < stageA; idx += nthr) {                        \
            int r = idx >> 5, kk = idx & 31;                                    \
            int k = kc + kk;                                                    \
            int row = m0 + r;                                                   \
            if (k < K && row < arows)                                           \
                cp4(smem_u32p(pA + idx), A + (size_t)row * AS + k);             \
            else pA[idx] = 0.0f;                                                \
        }                                                                       \
    } while (0)

    PREFETCH(0, 0);
    cp_commit();

    for (int ch = 0; ch < nch; ch++) {
        int buf = ch & 1;
        if (ch + 1 < nch) {
            PREFETCH(ch + 1, buf ^ 1);
            cp_commit();
            cp_wait<1>();
        } else {
            cp_wait<0>();
        }
        __syncthreads();

        const float* sW  = sm + buf * stride;
        const float* sAr = sW + stageW + threadIdx.y * R * KC;
        #pragma unroll 8
        for (int kk = 0; kk < KC; kk++) {
            float4 w = *reinterpret_cast<const float4*>(sW + kk * BN + g0);
            #pragma unroll
            for (int r = 0; r < R; r++) {
                float a = sAr[r * KC + kk];          // warp broadcast
                acc[r][0] = fmaf(a, w.x, acc[r][0]);
                acc[r][1] = fmaf(a, w.y, acc[r][1]);
                acc[r][2] = fmaf(a, w.z, acc[r][2]);
                acc[r][3] = fmaf(a, w.w, acc[r][3]);
            }
        }
        __syncthreads();
    }
    #undef PREFETCH

    float4 bv = make_float4(0.f, 0.f, 0.f, 0.f);
    if (bias) bv = *reinterpret_cast<const float4*>(bias + g0);
    int i0 = threadIdx.y * R;
    #pragma unroll
    for (int r = 0; r < R; r++) {
        int row = m0 + i0 + r;
        float4 v = make_float4(acc[r][0] + bv.x, acc[r][1] + bv.y,
                               acc[r][2] + bv.z, acc[r][3] + bv.w);
        if (do_relu) {
            v.x = fmaxf(v.x, 0.f); v.y = fmaxf(v.y, 0.f);
            v.z = fmaxf(v.z, 0.f); v.w = fmaxf(v.w, 0.f);
        }
        *reinterpret_cast<float4*>(C_ + (size_t)row * GP + g0) = v;
    }
}

// ---------------- spmm + relu, 4 cols/thread, 8-deep gather -----------------
__global__ void k_spmm4(const float* __restrict__ T, const float* __restrict__ bias,
                        float* __restrict__ O, int G) {
    int b = blockIdx.y;
    int i = blockIdx.x * blockDim.y + threadIdx.y;
    if (i >= NN) return;
    int row = b * NN + i;
    int g0 = threadIdx.x * 4;

    int cnt = g_nz_cnt[row];
    const ull* L = g_nz + (size_t)row * LSTR;
    const float* Tb = T + (size_t)b * NN * G + g0;

    ull acc0 = pk2(bias[g0], bias[g0 + 1]);
    ull acc1 = pk2(bias[g0 + 2], bias[g0 + 3]);
    for (int e = 0; e < cnt; e += 8) {
        ull p[8];
        #pragma unroll
        for (int u = 0; u < 8; u++) p[u] = L[e + u];
        ulonglong2 t[8];
        #pragma unroll
        for (int u = 0; u < 8; u++)
            t[u] = *(const ulonglong2*)(Tb + (size_t)(unsigned)p[u] * G);
        #pragma unroll
        for (int u = 0; u < 8; u++) {
            float v = __uint_as_float((unsigned)(p[u] >> 32));
            ull v2 = pk2(v, v);
            FMA2(acc0, t[u].x, v2);
            FMA2(acc1, t[u].y, v2);
        }
    }
    float h0, h1, h2, h3;
    upk2(acc0, h0, h1);
    upk2(acc1, h2, h3);
    float4 r = make_float4(fmaxf(h0, 0.f), fmaxf(h1, 0.f), fmaxf(h2, 0.f), fmaxf(h3, 0.f));
    *reinterpret_cast<float4*>(O + (size_t)row * G + g0) = r;
}

// ---------------- neighbor max-pool, 4 cols/thread, 8-deep ------------------
__global__ void k_pool4(const float* __restrict__ H, float* __restrict__ O, int G) {
    int b = blockIdx.y;
    int i = blockIdx.x * blockDim.y + threadIdx.y;
    if (i >= NN) return;
    int row = b * NN + i;
    int g0 = threadIdx.x * 4;

    int cnt = g_pl_cnt[row];
    const int* ji = g_pl_idx + (size_t)row * LSTR;
    const float4* Hb = reinterpret_cast<const float4*>(H + (size_t)b * NN * G + g0);
    int pitch = G >> 2;

    float4 m = make_float4(0.f, 0.f, 0.f, 0.f);
    for (int e = 0; e < cnt; e += 8) {
        int j[8];
        #pragma unroll
        for (int u = 0; u < 8; u++) j[u] = ji[e + u];
        float4 h[8];
        #pragma unroll
        for (int u = 0; u < 8; u++) h[u] = Hb[(size_t)j[u] * pitch];
        #pragma unroll
        for (int u = 0; u < 8; u++) {
            m.x = fmaxf(m.x, h[u].x);
            m.y = fmaxf(m.y, h[u].y);
            m.z = fmaxf(m.z, h[u].z);
            m.w = fmaxf(m.w, h[u].w);
        }
    }
    reinterpret_cast<float4*>(O + (size_t)row * G + g0)[0] = m;
}

// ---------------- head: gc4 + fc1 + fin + sigmoid ----------
__global__ void k_final(const float* __restrict__ P3,
                        const float* __restrict__ gc4_w,
                        const float* __restrict__ gc4_b,
                        const float* __restrict__ fc1_w,
                        const float* __restrict__ fc1_b,
                        const float* __restrict__ fin_w,
                        const float* __restrict__ fin_b,
                        float* __restrict__ out) {
    int b = blockIdx.x;
    int t = threadIdx.x;
    __shared__ float t4[NN];
    __shared__ float h[NN];
    __shared__ float rr[3];

    if (t < NN) {
        const float* p = P3 + (size_t)(b * NN + t) * GP3;
        float a = 0.0f;
        #pragma unroll
        for (int k = 0; k < F0; k++) a = fmaf(p[k], gc4_w[k], a);
        t4[t] = a;
    }
    __syncthreads();

    if (t < NN) {
        int row = b * NN + t;
        int cnt = g_nz_cnt[row];
        const ull* L = g_nz + (size_t)row * LSTR;
        float acc = gc4_b[0];
        for (int e = 0; e < cnt; e++) {
            ull p = L[e];
            acc = fmaf(__uint_as_float((unsigned)(p >> 32)), t4[(int)(unsigned)p], acc);
        }
        h[t] = fmaxf(acc, 0.0f);
    }
    __syncthreads();

    if (t < 3) {
        float a = fc1_b[t];
        for (int k = 0; k < NN - 1; k++)
            a = fmaf(h[k + 1], fc1_w[k * 3 + t], a);
        rr[t] = a;
    }
    __syncthreads();

    if (t == 0) {
        float z = h[0] * fin_w[0] + rr[0] * fin_w[1] + rr[1] * fin_w[2]
                + rr[2] * fin_w[3] + fin_b[0];
        out[b] = 1.0f / (1.0f + expf(-z));
    }
}

// ---------------- launch ----------------
extern "C" void kernel_launch(void* const* d_in, const int* in_sizes, int n_in,
                              void* d_out, int out_size) {
    const float* x     = (const float*)d_in[0];
    const float* adj   = (const float*)d_in[1];
    const float* emb_w = (const float*)d_in[2];
    const float* emb_b = (const float*)d_in[3];
    const float* gc1_w = (const float*)d_in[4];
    const float* gc1_b = (const float*)d_in[5];
    const float* gc2_w = (const float*)d_in[6];
    const float* gc2_b = (const float*)d_in[7];
    const float* gc3_w = (const float*)d_in[8];
    const float* gc3_b = (const float*)d_in[9];
    const float* gc4_w = (const float*)d_in[10];
    const float* gc4_b = (const float*)d_in[11];
    const float* fc1_w = (const float*)d_in[12];
    const float* fc1_b = (const float*)d_in[13];
    const float* fin_w = (const float*)d_in[14];
    const float* fin_b = (const float*)d_in[15];
    float* out = (float*)d_out;

    float *dA, *dB, *dEw, *dEb, *d3w, *db3;
    cudaGetSymbolAddress((void**)&dA,  g_bufA);
    cudaGetSymbolAddress((void**)&dB,  g_bufB);
    cudaGetSymbolAddress((void**)&dEw, g_embw);
    cudaGetSymbolAddress((void**)&dEb, g_embb);
    cudaGetSymbolAddress((void**)&d3w, g_gc3w);
    cudaGetSymbolAddress((void**)&db3, g_b3pad);

    cudaFuncSetAttribute(k_dense_db<8>,
                         cudaFuncAttributeMaxDynamicSharedMemorySize, 84000);

    // 0) sparse lists + weight padding (fused)
    {
        int warps_per_blk = 8;
        int blocks = (NROW + warps_per_blk - 1) / warps_per_blk;
        k_build_lists<<<blocks, warps_per_blk * 32>>>(adj, emb_w, emb_b, gc3_w, gc3_b);
    }

    const int KC = 32;
    // smem bytes: 2 stages of (KC*G + nrows*KC); nrows = 64 for all
    int sm_emb = 2 * (KC * GP1 + 64 * KC) * 4;   // 55296
    int sm_gc1 = 2 * (KC * H1  + 64 * KC) * 4;   // 81920
    int sm_gc2 = 2 * (KC * H2  + 64 * KC) * 4;   // 49152
    int sm_gc3 = 2 * (KC * GP3 + 64 * KC) * 4;   // 35840

    // All dense: R=8, nrows=64, grid = MPAD/64 = 148 (1 block/SM, single wave)
    // 1) emb: dA = relu(x @ embw_pad + embb_pad)   [MPAD,152]
    k_dense_db<8><<<148, dim3(38, 8), sm_emb>>>(x, dEw, dEb, dA, F0, F0, GP1, GP1, 1, NROW);
    // 2) dB = dA @ gc1_w                           [MPAD,256] (A stride 152)
    k_dense_db<8><<<148, dim3(64, 8), sm_gc1>>>(dA, gc1_w, nullptr, dB, F1, GP1, H1, H1, 0, MPAD);
    // 3) dA = relu(adj.dB + gc1_b)
    k_spmm4<<<dim3(34, BB), dim3(64, 4)>>>(dB, gc1_b, dA, H1);
    // 4) dB = pool(dA)
    k_pool4<<<dim3(34, BB), dim3(64, 4)>>>(dA, dB, H1);
    // 5) dA = dB @ gc2_w                           [MPAD,128]
    k_dense_db<8><<<148, dim3(32, 8), sm_gc2>>>(dB, gc2_w, nullptr, dA, H1, H1, H2, H2, 0, MPAD);
    // 6) dB = relu(adj.dA + gc2_b)
    k_spmm4<<<dim3(17, BB), dim3(32, 8)>>>(dA, gc2_b, dB, H2);
    // 7) dA = pool(dB)
    k_pool4<<<dim3(17, BB), dim3(32, 8)>>>(dB, dA, H2);
    // 8) dB = dA @ gc3w_pad                        [MPAD,76]
    k_dense_db<8><<<148, dim3(19, 8), sm_gc3>>>(dA, d3w, nullptr, dB, H2, H2, GP3, GP3, 0, MPAD);
    // 9) dA = relu(adj.dB + b3pad)                 [.,76]
    k_spmm4<<<dim3(17, BB), dim3(19, 8)>>>(dB, db3, dA, GP3);
    // 10) dB = pool(dA)                            [.,76]
    k_pool4<<<dim3(17, BB), dim3(19, 8)>>>(dA, dB, GP3);
    // 11) head
    k_final<<<BB, 160>>>(dB, gc4_w, gc4_b, fc1_w, fc1_b, fin_w, fin_b, out);
}

// round 15
// speedup vs baseline: 1.2260x; 1.0684x over previous
#include <cuda_runtime.h>
#include <math.h>

typedef unsigned long long ull;

// Problem dims
#define BB 64
#define NN 133
#define NROW (BB*NN)      // 8512 real rows
#define MPAD 9472         // 64 * 148: dense grid = 148 = 1 block/SM
#define F0 75
#define F1 150
#define H1 256
#define H2 128
#define GP1 152
#define GP3 76
#define LSTR 136
#define APITCH 66         // transposed A-tile pitch (even => aligned LDS.64 pairs)

// ---------------- scratch ----------------
__device__ float g_bufA[(size_t)MPAD * 256];
__device__ float g_bufB[(size_t)MPAD * 256];

__device__ float g_embw[F0 * GP1];
__device__ float g_embb[GP1];
__device__ float g_gc3w[H2 * GP3];
__device__ float g_b3pad[GP3];

__device__ int   g_nz_cnt[NROW];
__device__ ull   g_nz[(size_t)NROW * LSTR];
__device__ int   g_pl_cnt[NROW];
__device__ int   g_pl_idx[(size_t)NROW * LSTR];

// ---------------- f32x2 helpers ----------------
__device__ __forceinline__ ull pk2(float x, float y) {
    ull r;
    asm("mov.b64 %0, {%1, %2};" : "=l"(r) : "f"(x), "f"(y));
    return r;
}
__device__ __forceinline__ void upk2(ull v, float& x, float& y) {
    asm("mov.b64 {%0, %1}, %2;" : "=f"(x), "=f"(y) : "l"(v));
}
#define FMA2(acc, a, b) asm("fma.rn.f32x2 %0, %1, %2, %0;" : "+l"(acc) : "l"(a), "l"(b))

// ---------------- cp.async helpers ----------------
__device__ __forceinline__ unsigned smem_u32p(const void* p) {
    return (unsigned)__cvta_generic_to_shared(p);
}
__device__ __forceinline__ void cp16(unsigned dst, const void* src) {
    asm volatile("cp.async.ca.shared.global [%0], [%1], 16;" :: "r"(dst), "l"(src));
}
__device__ __forceinline__ void cp4(unsigned dst, const void* src) {
    asm volatile("cp.async.ca.shared.global [%0], [%1], 4;" :: "r"(dst), "l"(src));
}
__device__ __forceinline__ void cp_commit() {
    asm volatile("cp.async.commit_group;" ::: "memory");
}
template<int N>
__device__ __forceinline__ void cp_wait() {
    asm volatile("cp.async.wait_group %0;" :: "n"(N) : "memory");
}

// ---------------- build sparse lists + weight padding (fused) ----------------
#define PAD_T0 (F0*GP1)
#define PAD_T1 (PAD_T0 + GP1)
#define PAD_T2 (PAD_T1 + H2*GP3)
#define PAD_T3 (PAD_T2 + GP3)
__global__ void k_build_lists(const float* __restrict__ adj,
                              const float* __restrict__ emb_w, const float* __restrict__ emb_b,
                              const float* __restrict__ gc3_w, const float* __restrict__ gc3_b) {
    int gtid = blockIdx.x * blockDim.x + threadIdx.x;
    if (gtid < PAD_T3) {
        int idx = gtid;
        if (idx < PAD_T0) {
            int g = idx % GP1;
            g_embw[idx] = (g < F1) ? emb_w[(idx / GP1) * F1 + g] : 0.0f;
        } else if (idx < PAD_T1) {
            int g = idx - PAD_T0;
            g_embb[g] = (g < F1) ? emb_b[g] : 0.0f;
        } else if (idx < PAD_T2) {
            int j = idx - PAD_T1;
            int g = j % GP3;
            g_gc3w[j] = (g < F0) ? gc3_w[(j / GP3) * F0 + g] : 0.0f;
        } else {
            int g = idx - PAD_T2;
            g_b3pad[g] = (g < F0) ? gc3_b[g] : 0.0f;
        }
    }

    int warp_in_blk = threadIdx.x >> 5;
    int lane = threadIdx.x & 31;
    int wg = blockIdx.x * (blockDim.x >> 5) + warp_in_blk;
    if (wg >= NROW) return;
    const float* arow = adj + (size_t)wg * NN;

    int cnz = 0, cpl = 0;
    int firstj = 0;
    unsigned lt = (1u << lane) - 1u;
    for (int base = 0; base < NN; base += 32) {
        int j = base + lane;
        float a = (j < NN) ? arow[j] : 0.0f;
        bool nz = (j < NN) && (a != 0.0f);
        bool pl = (j < NN) && (a > 1e-5f);
        unsigned mnz = __ballot_sync(0xffffffffu, nz);
        unsigned mpl = __ballot_sync(0xffffffffu, pl);
        if (nz) {
            int pos = cnz + __popc(mnz & lt);
            g_nz[(size_t)wg * LSTR + pos] =
                ((ull)__float_as_uint(a) << 32) | (unsigned)j;
        }
        if (pl) {
            int pos = cpl + __popc(mpl & lt);
            g_pl_idx[(size_t)wg * LSTR + pos] = j;
        }
        if (cpl == 0 && mpl) firstj = base + __ffs(mpl) - 1;
        cnz += __popc(mnz);
        cpl += __popc(mpl);
    }
    int pnz = (cnz + 7) & ~7;
    int ppl = (cpl + 7) & ~7;
    if (lane < pnz - cnz) g_nz[(size_t)wg * LSTR + cnz + lane] = 0ull;
    if (lane < ppl - cpl) g_pl_idx[(size_t)wg * LSTR + cpl + lane] = firstj;
    if (lane == 0) { g_nz_cnt[wg] = pnz; g_pl_cnt[wg] = ppl; }
}

// ---------------- dense GEMM: f32x2 dual-MAC, 4 row-pairs x 4 cols ----------
// C_[m,g] = A[m,:] @ W[:,g] (+bias, relu).  nrows = 64, grid 148, block (G/4, 8).
// A staged TRANSPOSED sAT[KC][APITCH]; row-pair reads are aligned LDS.64
// broadcasts. W staged as [KC][G]; per-k one LDS.128 + 4 (w,w) packs.
__global__ void k_dense_f2(const float* __restrict__ A, const float* __restrict__ W,
                           const float* __restrict__ bias, float* __restrict__ C_,
                           int K, int AS, int G, int GP, int do_relu, int arows) {
    const int KC = 32;
    const int NR = 64;                        // rows per block (8 per thread)
    extern __shared__ float sm[];
    int BN = blockDim.x * 4;                  // == G
    int stageW = KC * BN;
    int stageA = KC * APITCH;
    int stride = stageW + stageA;

    int m0   = blockIdx.x * NR;
    int tid  = threadIdx.y * blockDim.x + threadIdx.x;
    int nthr = blockDim.x * blockDim.y;
    int g0   = threadIdx.x * 4;
    int i0   = threadIdx.y * 8;               // even -> aligned pairs
    int nch  = (K + KC - 1) / KC;

    ull acc[4][4];                            // [row-pair][col]
    #pragma unroll
    for (int p = 0; p < 4; p++)
        #pragma unroll
        for (int c = 0; c < 4; c++) acc[p][c] = 0ull;

    #define PREFETCH(CH, BUF) do {                                              \
        float* pW = sm + (BUF) * stride;                                        \
        float* pA = pW + stageW;                                                \
        int kc = (CH) * KC;                                                     \
        for (int kk = threadIdx.y; kk < KC; kk += blockDim.y) {                 \
            int k = kc + kk;                                                    \
            float* d = pW + kk * BN + g0;                                       \
            if (k < K) cp16(smem_u32p(d), W + (size_t)k * G + g0);              \
            else *reinterpret_cast<float4*>(d) = make_float4(0.f,0.f,0.f,0.f);  \
        }                                                                       \
        for (int idx = tid; idx < NR * KC; idx += nthr) {                       \
            int r = idx >> 5, kk = idx & 31;   /* consecutive tid -> kk */      \
            int k = kc + kk;                                                    \
            int row = m0 + r;                                                   \
            float* d = pA + kk * APITCH + r;   /* transposed store */           \
            if (k < K && row < arows)                                           \
                cp4(smem_u32p(d), A + (size_t)row * AS + k);                    \
            else *d = 0.0f;                                                     \
        }                                                                       \
    } while (0)

    PREFETCH(0, 0);
    cp_commit();

    for (int ch = 0; ch < nch; ch++) {
        int buf = ch & 1;
        if (ch + 1 < nch) {
            PREFETCH(ch + 1, buf ^ 1);
            cp_commit();
            cp_wait<1>();
        } else {
            cp_wait<0>();
        }
        __syncthreads();

        const float* sW  = sm + buf * stride;
        const float* sAT = sW + stageW;
        #pragma unroll 8
        for (int kk = 0; kk < KC; kk++) {
            const float* ap = sAT + kk * APITCH + i0;
            ull a2[4];
            #pragma unroll
            for (int p = 0; p < 4; p++)
                a2[p] = *reinterpret_cast<const ull*>(ap + 2 * p);   // LDS.64 bcast
            float4 w = *reinterpret_cast<const float4*>(sW + kk * BN + g0);
            ull w2[4] = { pk2(w.x, w.x), pk2(w.y, w.y), pk2(w.z, w.z), pk2(w.w, w.w) };
            #pragma unroll
            for (int p = 0; p < 4; p++) {
                FMA2(acc[p][0], a2[p], w2[0]);
                FMA2(acc[p][1], a2[p], w2[1]);
                FMA2(acc[p][2], a2[p], w2[2]);
                FMA2(acc[p][3], a2[p], w2[3]);
            }
        }
        __syncthreads();
    }
    #undef PREFETCH

    float4 bv = make_float4(0.f, 0.f, 0.f, 0.f);
    if (bias) bv = *reinterpret_cast<const float4*>(bias + g0);
    #pragma unroll
    for (int p = 0; p < 4; p++) {
        float lo[4], hi[4];
        #pragma unroll
        for (int c = 0; c < 4; c++) upk2(acc[p][c], lo[c], hi[c]);
        int r0 = m0 + i0 + 2 * p;
        float4 v0 = make_float4(lo[0] + bv.x, lo[1] + bv.y, lo[2] + bv.z, lo[3] + bv.w);
        float4 v1 = make_float4(hi[0] + bv.x, hi[1] + bv.y, hi[2] + bv.z, hi[3] + bv.w);
        if (do_relu) {
            v0.x = fmaxf(v0.x, 0.f); v0.y = fmaxf(v0.y, 0.f);
            v0.z = fmaxf(v0.z, 0.f); v0.w = fmaxf(v0.w, 0.f);
            v1.x = fmaxf(v1.x, 0.f); v1.y = fmaxf(v1.y, 0.f);
            v1.z = fmaxf(v1.z, 0.f); v1.w = fmaxf(v1.w, 0.f);
        }
        *reinterpret_cast<float4*>(C_ + (size_t)r0 * GP + g0)       = v0;
        *reinterpret_cast<float4*>(C_ + (size_t)(r0 + 1) * GP + g0) = v1;
    }
}

// ---------------- spmm + relu, 4 cols/thread, 8-deep gather -----------------
__global__ void k_spmm4(const float* __restrict__ T, const float* __restrict__ bias,
                        float* __restrict__ O, int G) {
    int b = blockIdx.y;
    int i = blockIdx.x * blockDim.y + threadIdx.y;
    if (i >= NN) return;
    int row = b * NN + i;
    int g0 = threadIdx.x * 4;

    int cnt = g_nz_cnt[row];
    const ull* L = g_nz + (size_t)row * LSTR;
    const float* Tb = T + (size_t)b * NN * G + g0;

    ull acc0 = pk2(bias[g0], bias[g0 + 1]);
    ull acc1 = pk2(bias[g0 + 2], bias[g0 + 3]);
    for (int e = 0; e < cnt; e += 8) {
        ull p[8];
        #pragma unroll
        for (int u = 0; u < 8; u++) p[u] = L[e + u];
        ulonglong2 t[8];
        #pragma unroll
        for (int u = 0; u < 8; u++)
            t[u] = *(const ulonglong2*)(Tb + (size_t)(unsigned)p[u] * G);
        #pragma unroll
        for (int u = 0; u < 8; u++) {
            float v = __uint_as_float((unsigned)(p[u] >> 32));
            ull v2 = pk2(v, v);
            FMA2(acc0, t[u].x, v2);
            FMA2(acc1, t[u].y, v2);
        }
    }
    float h0, h1, h2, h3;
    upk2(acc0, h0, h1);
    upk2(acc1, h2, h3);
    float4 r = make_float4(fmaxf(h0, 0.f), fmaxf(h1, 0.f), fmaxf(h2, 0.f), fmaxf(h3, 0.f));
    *reinterpret_cast<float4*>(O + (size_t)row * G + g0) = r;
}

// ---------------- neighbor max-pool, 4 cols/thread, 8-deep ------------------
__global__ void k_pool4(const float* __restrict__ H, float* __restrict__ O, int G) {
    int b = blockIdx.y;
    int i = blockIdx.x * blockDim.y + threadIdx.y;
    if (i >= NN) return;
    int row = b * NN + i;
    int g0 = threadIdx.x * 4;

    int cnt = g_pl_cnt[row];
    const int* ji = g_pl_idx + (size_t)row * LSTR;
    const float4* Hb = reinterpret_cast<const float4*>(H + (size_t)b * NN * G + g0);
    int pitch = G >> 2;

    float4 m = make_float4(0.f, 0.f, 0.f, 0.f);
    for (int e = 0; e < cnt; e += 8) {
        int j[8];
        #pragma unroll
        for (int u = 0; u < 8; u++) j[u] = ji[e + u];
        float4 h[8];
        #pragma unroll
        for (int u = 0; u < 8; u++) h[u] = Hb[(size_t)j[u] * pitch];
        #pragma unroll
        for (int u = 0; u < 8; u++) {
            m.x = fmaxf(m.x, h[u].x);
            m.y = fmaxf(m.y, h[u].y);
            m.z = fmaxf(m.z, h[u].z);
            m.w = fmaxf(m.w, h[u].w);
        }
    }
    reinterpret_cast<float4*>(O + (size_t)row * G + g0)[0] = m;
}

// ---------------- head: gc4 + fc1 + fin + sigmoid ----------
__global__ void k_final(const float* __restrict__ P3,
                        const float* __restrict__ gc4_w,
                        const float* __restrict__ gc4_b,
                        const float* __restrict__ fc1_w,
                        const float* __restrict__ fc1_b,
                        const float* __restrict__ fin_w,
                        const float* __restrict__ fin_b,
                        float* __restrict__ out) {
    int b = blockIdx.x;
    int t = threadIdx.x;
    __shared__ float t4[NN];
    __shared__ float h[NN];
    __shared__ float rr[3];

    if (t < NN) {
        const float* p = P3 + (size_t)(b * NN + t) * GP3;
        float a = 0.0f;
        #pragma unroll
        for (int k = 0; k < F0; k++) a = fmaf(p[k], gc4_w[k], a);
        t4[t] = a;
    }
    __syncthreads();

    if (t < NN) {
        int row = b * NN + t;
        int cnt = g_nz_cnt[row];
        const ull* L = g_nz + (size_t)row * LSTR;
        float acc = gc4_b[0];
        for (int e = 0; e < cnt; e++) {
            ull p = L[e];
            acc = fmaf(__uint_as_float((unsigned)(p >> 32)), t4[(int)(unsigned)p], acc);
        }
        h[t] = fmaxf(acc, 0.0f);
    }
    __syncthreads();

    if (t < 3) {
        float a = fc1_b[t];
        for (int k = 0; k < NN - 1; k++)
            a = fmaf(h[k + 1], fc1_w[k * 3 + t], a);
        rr[t] = a;
    }
    __syncthreads();

    if (t == 0) {
        float z = h[0] * fin_w[0] + rr[0] * fin_w[1] + rr[1] * fin_w[2]
                + rr[2] * fin_w[3] + fin_b[0];
        out[b] = 1.0f / (1.0f + expf(-z));
    }
}

// ---------------- launch ----------------
extern "C" void kernel_launch(void* const* d_in, const int* in_sizes, int n_in,
                              void* d_out, int out_size) {
    const float* x     = (const float*)d_in[0];
    const float* adj   = (const float*)d_in[1];
    const float* emb_w = (const float*)d_in[2];
    const float* emb_b = (const float*)d_in[3];
    const float* gc1_w = (const float*)d_in[4];
    const float* gc1_b = (const float*)d_in[5];
    const float* gc2_w = (const float*)d_in[6];
    const float* gc2_b = (const float*)d_in[7];
    const float* gc3_w = (const float*)d_in[8];
    const float* gc3_b = (const float*)d_in[9];
    const float* gc4_w = (const float*)d_in[10];
    const float* gc4_b = (const float*)d_in[11];
    const float* fc1_w = (const float*)d_in[12];
    const float* fc1_b = (const float*)d_in[13];
    const float* fin_w = (const float*)d_in[14];
    const float* fin_b = (const float*)d_in[15];
    float* out = (float*)d_out;

    float *dA, *dB, *dEw, *dEb, *d3w, *db3;
    cudaGetSymbolAddress((void**)&dA,  g_bufA);
    cudaGetSymbolAddress((void**)&dB,  g_bufB);
    cudaGetSymbolAddress((void**)&dEw, g_embw);
    cudaGetSymbolAddress((void**)&dEb, g_embb);
    cudaGetSymbolAddress((void**)&d3w, g_gc3w);
    cudaGetSymbolAddress((void**)&db3, g_b3pad);

    cudaFuncSetAttribute(k_dense_f2,
                         cudaFuncAttributeMaxDynamicSharedMemorySize, 90112);

    // 0) sparse lists + weight padding (fused)
    {
        int warps_per_blk = 8;
        int blocks = (NROW + warps_per_blk - 1) / warps_per_blk;
        k_build_lists<<<blocks, warps_per_blk * 32>>>(adj, emb_w, emb_b, gc3_w, gc3_b);
    }

    const int KC = 32;
    // smem bytes: 2 stages of (KC*G + KC*APITCH)
    int sm_emb = 2 * (KC * GP1 + KC * APITCH) * 4;   // 55808
    int sm_gc1 = 2 * (KC * H1  + KC * APITCH) * 4;   // 82432
    int sm_gc2 = 2 * (KC * H2  + KC * APITCH) * 4;   // 49664
    int sm_gc3 = 2 * (KC * GP3 + KC * APITCH) * 4;   // 36352

    // All dense: 64 rows/block, grid 148, block (G/4, 8)
    // 1) emb: dA = relu(x @ embw_pad + embb_pad)   [MPAD,152]
    k_dense_f2<<<148, dim3(38, 8), sm_emb>>>(x, dEw, dEb, dA, F0, F0, GP1, GP1, 1, NROW);
    // 2) dB = dA @ gc1_w                           [MPAD,256]
    k_dense_f2<<<148, dim3(64, 8), sm_gc1>>>(dA, gc1_w, nullptr, dB, F1, GP1, H1, H1, 0, MPAD);
    // 3) dA = relu(adj.dB + gc1_b)
    k_spmm4<<<dim3(34, BB), dim3(64, 4)>>>(dB, gc1_b, dA, H1);
    // 4) dB = pool(dA)
    k_pool4<<<dim3(34, BB), dim3(64, 4)>>>(dA, dB, H1);
    // 5) dA = dB @ gc2_w                           [MPAD,128]
    k_dense_f2<<<148, dim3(32, 8), sm_gc2>>>(dB, gc2_w, nullptr, dA, H1, H1, H2, H2, 0, MPAD);
    // 6) dB = relu(adj.dA + gc2_b)
    k_spmm4<<<dim3(17, BB), dim3(32, 8)>>>(dA, gc2_b, dB, H2);
    // 7) dA = pool(dB)
    k_pool4<<<dim3(17, BB), dim3(32, 8)>>>(dB, dA, H2);
    // 8) dB = dA @ gc3w_pad                        [MPAD,76]
    k_dense_f2<<<148, dim3(19, 8), sm_gc3>>>(dA, d3w, nullptr, dB, H2, H2, GP3, GP3, 0, MPAD);
    // 9) dA = relu(adj.dB + b3pad)                 [.,76]
    k_spmm4<<<dim3(17, BB), dim3(19, 8)>>>(dB, db3, dA, GP3);
    // 10) dB = pool(dA)                            [.,76]
    k_pool4<<<dim3(17, BB), dim3(19, 8)>>>(dA, dB, GP3);
    // 11) head
    k_final<<<BB, 160>>>(dB, gc4_w, gc4_b, fc1_w, fc1_b, fin_w, fin_b, out);
}